// round 1
// baseline (speedup 1.0000x reference)
#include <cuda_runtime.h>
#include <math.h>

#define NN      50000
#define NE      800000
#define TE      (NE + NN)      // edges + self loops
#define GG      512
#define IN_DIM  128
#define HIDD    256
#define HEADS   8
#define NEG_SLOPE 0.2f
#define BN_EPS  1e-5f

// ---------------- scratch (static device globals; no runtime alloc) ----------------
__device__ float d_hl[NN * HIDD];        // linear output of current layer (h = x@W)
__device__ float d_actbuf[NN * HIDD];    // activation (layer input / output)
__device__ float d_ssrc[NN * HEADS];
__device__ float d_sdst[NN * HEADS];
__device__ int   d_off[NN + 1];          // CSR offsets (counts during build)
__device__ int   d_cur[NN];              // scatter cursors
__device__ int   d_es[TE];               // src node per CSR slot (grouped by dst)

static inline int cdiv(int a, int b) { return (a + b - 1) / b; }

// ---------------- CSR build ----------------
__global__ void k_init_deg() {
    int n = blockIdx.x * blockDim.x + threadIdx.x;
    if (n < NN) d_off[n] = 1;            // self loop
}

__global__ void k_count(const int* __restrict__ dst) {
    int e = blockIdx.x * blockDim.x + threadIdx.x;
    if (e < NE) atomicAdd(&d_off[dst[e]], 1);
}

__global__ void k_scan() {
    __shared__ int s[1024];
    const int CH = (NN + 1023) / 1024;   // 49
    int t = threadIdx.x;
    int b = t * CH;
    int e = b + CH; if (e > NN) e = NN;
    int sum = 0;
    for (int i = b; i < e && i < NN; i++) sum += d_off[i];
    s[t] = sum;
    __syncthreads();
    for (int o = 1; o < 1024; o <<= 1) {
        int v = (t >= o) ? s[t - o] : 0;
        __syncthreads();
        s[t] += v;
        __syncthreads();
    }
    int run = s[t] - sum;                // exclusive prefix
    for (int i = b; i < e && i < NN; i++) {
        int c = d_off[i];
        d_off[i] = run;
        d_cur[i] = run;
        run += c;
    }
    if (t == 0) d_off[NN] = TE;
}

__global__ void k_scatter(const int* __restrict__ src, const int* __restrict__ dst) {
    int e = blockIdx.x * blockDim.x + threadIdx.x;
    if (e < NE) {
        int d = dst[e];
        int pos = atomicAdd(&d_cur[d], 1);
        d_es[pos] = src[e];
    } else if (e < TE) {
        int n = e - NE;                   // self loop
        int pos = atomicAdd(&d_cur[n], 1);
        d_es[pos] = n;
    }
}

// ---------------- fp32 SGEMM: C[M,256] = A[M,K] @ B[K,256] ----------------
// BM=128, BN=128, BK=8, 256 threads, 8x8 micro-tile per thread.
__global__ void __launch_bounds__(256) k_sgemm(const float* __restrict__ Aext, int useAct,
                                               const float* __restrict__ B, int M, int K) {
    const float* __restrict__ A = useAct ? (const float*)d_actbuf : Aext;
    __shared__ float As[8][132];
    __shared__ float Bs[8][128];

    int tid = threadIdx.x;
    int bm0 = blockIdx.x * 128;
    int bn0 = blockIdx.y * 128;
    int tx = tid & 15;            // col group
    int ty = tid >> 4;            // row group

    int arow = tid >> 1;
    int akc  = (tid & 1) * 4;
    int brow = tid >> 5;
    int bcol = (tid & 31) * 4;
    bool avalid = (bm0 + arow) < M;
    const float* Ap = A + (size_t)(bm0 + arow) * K + akc;
    const float* Bp = B + (size_t)brow * 256 + bn0 + bcol;

    float acc[8][8];
#pragma unroll
    for (int i = 0; i < 8; i++)
#pragma unroll
        for (int j = 0; j < 8; j++) acc[i][j] = 0.f;

    for (int k0 = 0; k0 < K; k0 += 8) {
        float4 a = avalid ? *(const float4*)(Ap + k0) : make_float4(0.f, 0.f, 0.f, 0.f);
        float4 b = *(const float4*)(Bp + (size_t)k0 * 256);
        As[akc + 0][arow] = a.x;
        As[akc + 1][arow] = a.y;
        As[akc + 2][arow] = a.z;
        As[akc + 3][arow] = a.w;
        *(float4*)&Bs[brow][bcol] = b;
        __syncthreads();
#pragma unroll
        for (int k = 0; k < 8; k++) {
            float4 a0 = *(const float4*)&As[k][ty * 8];
            float4 a1 = *(const float4*)&As[k][ty * 8 + 4];
            float4 b0 = *(const float4*)&Bs[k][tx * 8];
            float4 b1 = *(const float4*)&Bs[k][tx * 8 + 4];
            float av[8] = {a0.x, a0.y, a0.z, a0.w, a1.x, a1.y, a1.z, a1.w};
            float bv[8] = {b0.x, b0.y, b0.z, b0.w, b1.x, b1.y, b1.z, b1.w};
#pragma unroll
            for (int i = 0; i < 8; i++)
#pragma unroll
                for (int j = 0; j < 8; j++) acc[i][j] += av[i] * bv[j];
        }
        __syncthreads();
    }

#pragma unroll
    for (int i = 0; i < 8; i++) {
        int r = bm0 + ty * 8 + i;
        if (r < M) {
            float4 o0 = make_float4(acc[i][0], acc[i][1], acc[i][2], acc[i][3]);
            float4 o1 = make_float4(acc[i][4], acc[i][5], acc[i][6], acc[i][7]);
            *(float4*)&d_hl[(size_t)r * 256 + bn0 + tx * 8] = o0;
            *(float4*)&d_hl[(size_t)r * 256 + bn0 + tx * 8 + 4] = o1;
        }
    }
}

// ---------------- attention scores: s[n,h] = sum_c hl[n,h,c]*a[h,c] ----------------
__global__ void k_scores(const float* __restrict__ asrc, const float* __restrict__ adst) {
    int warp = (blockIdx.x * blockDim.x + threadIdx.x) >> 5;
    int lane = threadIdx.x & 31;
    if (warp >= NN) return;
    int n = warp;
    const float4* hl4 = (const float4*)d_hl;
    float4 x0 = hl4[(size_t)n * 64 + lane * 2];
    float4 x1 = hl4[(size_t)n * 64 + lane * 2 + 1];
    const float4* as4 = (const float4*)asrc;
    const float4* ad4 = (const float4*)adst;
    float4 s0 = as4[lane * 2], s1 = as4[lane * 2 + 1];
    float4 t0 = ad4[lane * 2], t1 = ad4[lane * 2 + 1];
    float ps = x0.x * s0.x + x0.y * s0.y + x0.z * s0.z + x0.w * s0.w
             + x1.x * s1.x + x1.y * s1.y + x1.z * s1.z + x1.w * s1.w;
    float pd = x0.x * t0.x + x0.y * t0.y + x0.z * t0.z + x0.w * t0.w
             + x1.x * t1.x + x1.y * t1.y + x1.z * t1.z + x1.w * t1.w;
    ps += __shfl_xor_sync(~0u, ps, 1); ps += __shfl_xor_sync(~0u, ps, 2);
    pd += __shfl_xor_sync(~0u, pd, 1); pd += __shfl_xor_sync(~0u, pd, 2);
    if ((lane & 3) == 0) {
        int h = lane >> 2;
        d_ssrc[n * 8 + h] = ps;
        d_sdst[n * 8 + h] = pd;
    }
}

__device__ __forceinline__ float leaky(float x) { return x > 0.f ? x : NEG_SLOPE * x; }

// ---------------- aggregation (warp per dst node) + bias + BN + res + ELU ----------------
__global__ void k_agg(const float* __restrict__ bias, const float* __restrict__ gam,
                      const float* __restrict__ bet, const float* __restrict__ mu,
                      const float* __restrict__ var, int useRes) {
    int warp = (blockIdx.x * blockDim.x + threadIdx.x) >> 5;
    int lane = threadIdx.x & 31;
    if (warp >= NN) return;
    int n = warp;
    int beg = d_off[n], end = d_off[n + 1];
    int h = lane >> 2;

    float sd8[8];
    {
        const float4* p = (const float4*)(d_sdst + n * 8);
        float4 a = p[0], b = p[1];
        sd8[0] = a.x; sd8[1] = a.y; sd8[2] = a.z; sd8[3] = a.w;
        sd8[4] = b.x; sd8[5] = b.y; sd8[6] = b.z; sd8[7] = b.w;
    }
    float m8[8], z8[8];
#pragma unroll
    for (int i = 0; i < 8; i++) { m8[i] = -1e30f; z8[i] = 0.f; }

    // online softmax stats (per-lane over its strided edges)
    for (int e = beg + lane; e < end; e += 32) {
        int s = d_es[e];
        const float4* p = (const float4*)(d_ssrc + s * 8);
        float4 a = p[0], b = p[1];
        float sv[8] = {a.x, a.y, a.z, a.w, b.x, b.y, b.z, b.w};
#pragma unroll
        for (int i = 0; i < 8; i++) {
            float al = leaky(sv[i] + sd8[i]);
            float mn = fmaxf(m8[i], al);
            z8[i] = z8[i] * __expf(m8[i] - mn) + __expf(al - mn);
            m8[i] = mn;
        }
    }
    // combine across lanes
#pragma unroll
    for (int i = 0; i < 8; i++) {
        float m = m8[i], z = z8[i];
#pragma unroll
        for (int o = 16; o; o >>= 1) {
            float mo = __shfl_xor_sync(~0u, m, o);
            float zo = __shfl_xor_sync(~0u, z, o);
            float mn = fmaxf(m, mo);
            z = z * __expf(m - mn) + zo * __expf(mo - mn);
            m = mn;
        }
        m8[i] = m; z8[i] = z;
    }
    float my_m = 0.f, my_z = 0.f, my_sd = 0.f;
#pragma unroll
    for (int i = 0; i < 8; i++)
        if (h == i) { my_m = m8[i]; my_z = z8[i]; my_sd = sd8[i]; }
    float inv = 1.f / (my_z + 1e-16f);

    const float4* hl4 = (const float4*)d_hl;
    float4 acc0 = make_float4(0.f, 0.f, 0.f, 0.f);
    float4 acc1 = make_float4(0.f, 0.f, 0.f, 0.f);
    for (int e = beg; e < end; e++) {
        int s = d_es[e];
        float sv = __ldg(d_ssrc + s * 8 + h);
        float coef = __expf(leaky(sv + my_sd) - my_m) * inv;
        float4 v0 = hl4[(size_t)s * 64 + lane * 2];
        float4 v1 = hl4[(size_t)s * 64 + lane * 2 + 1];
        acc0.x += v0.x * coef; acc0.y += v0.y * coef;
        acc0.z += v0.z * coef; acc0.w += v0.w * coef;
        acc1.x += v1.x * coef; acc1.y += v1.y * coef;
        acc1.z += v1.z * coef; acc1.w += v1.w * coef;
    }

    // epilogue: columns lane*8 .. lane*8+7
    int col = lane * 8;
    float4 b0 = *(const float4*)(bias + col), b1 = *(const float4*)(bias + col + 4);
    float4 g0 = *(const float4*)(gam + col),  g1 = *(const float4*)(gam + col + 4);
    float4 e0 = *(const float4*)(bet + col),  e1 = *(const float4*)(bet + col + 4);
    float4 u0 = *(const float4*)(mu + col),   u1 = *(const float4*)(mu + col + 4);
    float4 w0 = *(const float4*)(var + col),  w1 = *(const float4*)(var + col + 4);
    float4* act4 = (float4*)d_actbuf;
    float4 r0 = make_float4(0.f, 0.f, 0.f, 0.f), r1 = r0;
    if (useRes) {
        r0 = act4[(size_t)n * 64 + lane * 2];
        r1 = act4[(size_t)n * 64 + lane * 2 + 1];
    }
    float vin[8]  = {acc0.x, acc0.y, acc0.z, acc0.w, acc1.x, acc1.y, acc1.z, acc1.w};
    float bb[8]   = {b0.x, b0.y, b0.z, b0.w, b1.x, b1.y, b1.z, b1.w};
    float gg_[8]  = {g0.x, g0.y, g0.z, g0.w, g1.x, g1.y, g1.z, g1.w};
    float ee_[8]  = {e0.x, e0.y, e0.z, e0.w, e1.x, e1.y, e1.z, e1.w};
    float uu[8]   = {u0.x, u0.y, u0.z, u0.w, u1.x, u1.y, u1.z, u1.w};
    float vv[8]   = {w0.x, w0.y, w0.z, w0.w, w1.x, w1.y, w1.z, w1.w};
    float rr[8]   = {r0.x, r0.y, r0.z, r0.w, r1.x, r1.y, r1.z, r1.w};
    float outv[8];
#pragma unroll
    for (int j = 0; j < 8; j++) {
        float v = vin[j] + bb[j];
        v = (v - uu[j]) * rsqrtf(vv[j] + BN_EPS) * gg_[j] + ee_[j];
        if (useRes) v += rr[j];
        outv[j] = v > 0.f ? v : expm1f(v);
    }
    act4[(size_t)n * 64 + lane * 2]     = make_float4(outv[0], outv[1], outv[2], outv[3]);
    act4[(size_t)n * 64 + lane * 2 + 1] = make_float4(outv[4], outv[5], outv[6], outv[7]);
}

// ---------------- pooling + output heads ----------------
__device__ __forceinline__ int lbound(const int* __restrict__ a, int n, int v) {
    int lo = 0, hi = n;
    while (lo < hi) {
        int mid = (lo + hi) >> 1;
        if (a[mid] < v) lo = mid + 1; else hi = mid;
    }
    return lo;
}

__global__ void k_pool(const int* __restrict__ batch,
                       const float* __restrict__ ow0, const float* __restrict__ ob0,
                       const float* __restrict__ ow1, const float* __restrict__ ob1,
                       float* __restrict__ out) {
    int g = blockIdx.x;
    int t = threadIdx.x;
    int lo = lbound(batch, NN, g);
    int hi = lbound(batch, NN, g + 1);
    __shared__ float pooled[3 * HIDD];
    __shared__ float sacc[6];

    int c = t;  // 0..255
    float sum = 0.f, mx = -1e30f;
    for (int n = lo; n < hi; n++) {
        float v = d_actbuf[(size_t)n * 256 + c];
        sum += v;
        mx = fmaxf(mx, v);
    }
    int cnt = hi - lo;
    pooled[c]       = sum / fmaxf((float)cnt, 1.f);  // mean
    pooled[256 + c] = sum;                            // add
    pooled[512 + c] = (cnt > 0) ? mx : 0.f;           // max
    if (t < 6) sacc[t] = 0.f;
    __syncthreads();

    float p0[3] = {0.f, 0.f, 0.f}, p1[3] = {0.f, 0.f, 0.f};
    for (int j = t; j < 768; j += 256) {
        float v = pooled[j];
#pragma unroll
        for (int k = 0; k < 3; k++) {
            p0[k] += v * ow0[j * 3 + k];
            p1[k] += v * ow1[j * 3 + k];
        }
    }
#pragma unroll
    for (int k = 0; k < 3; k++) {
        atomicAdd(&sacc[k], p0[k]);
        atomicAdd(&sacc[3 + k], p1[k]);
    }
    __syncthreads();
    if (t < 3) {
        out[g * 3 + t]            = sacc[t]     + ob0[t];
        out[GG * 3 + g * 3 + t]   = sacc[3 + t] + ob1[t];
    }
}

// ---------------- launch ----------------
extern "C" void kernel_launch(void* const* d_in, const int* in_sizes, int n_in,
                              void* d_out, int out_size) {
    const float* x     = (const float*)d_in[0];
    const int*   ei    = (const int*)d_in[1];   // [2, E] row-major: src then dst
    const int*   batch = (const int*)d_in[2];

    const float* W[3]  = {(const float*)d_in[3],  (const float*)d_in[11], (const float*)d_in[19]};
    const float* AS[3] = {(const float*)d_in[4],  (const float*)d_in[12], (const float*)d_in[20]};
    const float* AD[3] = {(const float*)d_in[5],  (const float*)d_in[13], (const float*)d_in[21]};
    const float* BI[3] = {(const float*)d_in[6],  (const float*)d_in[14], (const float*)d_in[22]};
    const float* GA[3] = {(const float*)d_in[7],  (const float*)d_in[15], (const float*)d_in[23]};
    const float* BE[3] = {(const float*)d_in[8],  (const float*)d_in[16], (const float*)d_in[24]};
    const float* MU[3] = {(const float*)d_in[9],  (const float*)d_in[17], (const float*)d_in[25]};
    const float* VA[3] = {(const float*)d_in[10], (const float*)d_in[18], (const float*)d_in[26]};
    const float* ow0 = (const float*)d_in[27];
    const float* ob0 = (const float*)d_in[28];
    const float* ow1 = (const float*)d_in[29];
    const float* ob1 = (const float*)d_in[30];
    float* out = (float*)d_out;

    // CSR build (structure is input-dependent; rebuilt every call, deterministic work)
    k_init_deg<<<cdiv(NN, 256), 256>>>();
    k_count<<<cdiv(NE, 256), 256>>>(ei + NE);
    k_scan<<<1, 1024>>>();
    k_scatter<<<cdiv(TE, 256), 256>>>(ei, ei + NE);

    int K = IN_DIM;
    int useAct = 0;
    for (int l = 0; l < 3; l++) {
        dim3 gg(cdiv(NN, 128), 2);
        k_sgemm<<<gg, 256>>>(x, useAct, W[l], NN, K);
        k_scores<<<cdiv(NN, 8), 256>>>(AS[l], AD[l]);
        k_agg<<<cdiv(NN, 8), 256>>>(BI[l], GA[l], BE[l], MU[l], VA[l], l > 0 ? 1 : 0);
        K = HIDD;
        useAct = 1;
    }
    k_pool<<<GG, 256>>>(batch, ow0, ob0, ow1, ob1, out);
}

// round 3
// speedup vs baseline: 1.3233x; 1.3233x over previous
#include <cuda_runtime.h>
#include <cuda_bf16.h>
#include <math.h>
#include <stdint.h>

#define NN      50000
#define NE      800000
#define TE      (NE + NN)
#define GG      512
#define IN_DIM  128
#define HIDD    256
#define HEADS   8
#define NEG_SLOPE 0.2f
#define BN_EPS  1e-5f

#define BM 128
#define BN 128
#define BK 64
#define NPAD    50176                    // 392*128, padded rows read as zeros
#define NTILES  ((NN + BM - 1) / BM)     // 391

// SMEM stage layout (bf16, 72-element rows = 144B, conflict-free)
#define ROWB   144
#define TILEB  (128 * ROWB)              // 18432
#define AHO    0
#define ALO    TILEB
#define BHO    (2 * TILEB)
#define BLO    (3 * TILEB)
#define SSZ    (4 * TILEB)               // 73728 per stage
#define SMEM_TOTAL (2 * SSZ)             // 147456

// ---------------- scratch ----------------
__device__ float d_hl[NN * HIDD];
__device__ float d_actbuf[NN * HIDD];
__device__ float d_ssrc[NN * HEADS];
__device__ float d_sdst[NN * HEADS];
__device__ __nv_bfloat16 d_abh[NPAD * HIDD];
__device__ __nv_bfloat16 d_abl[NPAD * HIDD];
__device__ __nv_bfloat16 d_wbh[HIDD * HIDD];
__device__ __nv_bfloat16 d_wbl[HIDD * HIDD];
__device__ int d_off[NN + 1];
__device__ int d_cur[NN];
__device__ int d_es[TE];

static inline int cdiv(int a, int b) { return (a + b - 1) / b; }

// ---------------- CSR build ----------------
__global__ void k_init_deg() {
    int n = blockIdx.x * blockDim.x + threadIdx.x;
    if (n < NN) d_off[n] = 1;
}
__global__ void k_count(const int* __restrict__ dst) {
    int e = blockIdx.x * blockDim.x + threadIdx.x;
    if (e < NE) atomicAdd(&d_off[dst[e]], 1);
}
__global__ void k_scan() {
    __shared__ int s[1024];
    const int CH = (NN + 1023) / 1024;
    int t = threadIdx.x;
    int b = t * CH;
    int e = b + CH; if (e > NN) e = NN;
    int sum = 0;
    for (int i = b; i < e && i < NN; i++) sum += d_off[i];
    s[t] = sum;
    __syncthreads();
    for (int o = 1; o < 1024; o <<= 1) {
        int v = (t >= o) ? s[t - o] : 0;
        __syncthreads();
        s[t] += v;
        __syncthreads();
    }
    int run = s[t] - sum;
    for (int i = b; i < e && i < NN; i++) {
        int c = d_off[i];
        d_off[i] = run;
        d_cur[i] = run;
        run += c;
    }
    if (t == 0) d_off[NN] = TE;
}
__global__ void k_scatter(const int* __restrict__ src, const int* __restrict__ dst) {
    int e = blockIdx.x * blockDim.x + threadIdx.x;
    if (e < NE) {
        int d = dst[e];
        int pos = atomicAdd(&d_cur[d], 1);
        d_es[pos] = src[e];
    } else if (e < TE) {
        int n = e - NE;
        int pos = atomicAdd(&d_cur[n], 1);
        d_es[pos] = n;
    }
}

// ---------------- input/weight bf16 split ----------------
__global__ void k_cvtA(const float* __restrict__ x) {
    int idx = blockIdx.x * blockDim.x + threadIdx.x;   // over NN*IN_DIM/4
    if (idx >= NN * IN_DIM / 4) return;
    float4 v = ((const float4*)x)[idx];
    float vv[4] = {v.x, v.y, v.z, v.w};
    unsigned short h[4], l[4];
#pragma unroll
    for (int j = 0; j < 4; j++) {
        __nv_bfloat16 hb = __float2bfloat16(vv[j]);
        __nv_bfloat16 lb = __float2bfloat16(vv[j] - __bfloat162float(hb));
        h[j] = __bfloat16_as_ushort(hb);
        l[j] = __bfloat16_as_ushort(lb);
    }
    uint2 ph = make_uint2((uint32_t)h[0] | ((uint32_t)h[1] << 16),
                          (uint32_t)h[2] | ((uint32_t)h[3] << 16));
    uint2 pl = make_uint2((uint32_t)l[0] | ((uint32_t)l[1] << 16),
                          (uint32_t)l[2] | ((uint32_t)l[3] << 16));
    *(uint2*)(d_abh + (size_t)idx * 4) = ph;
    *(uint2*)(d_abl + (size_t)idx * 4) = pl;
}

// W[k][n] fp32 -> d_wbh/d_wbl[n][k] bf16 (transpose + split)
__global__ void k_prepW(const float* __restrict__ W, int K) {
    int idx = blockIdx.x * blockDim.x + threadIdx.x;
    if (idx >= K * HIDD) return;
    int k = idx / HIDD, n = idx % HIDD;
    float v = W[idx];
    __nv_bfloat16 hb = __float2bfloat16(v);
    __nv_bfloat16 lb = __float2bfloat16(v - __bfloat162float(hb));
    d_wbh[n * K + k] = hb;
    d_wbl[n * K + k] = lb;
}

// ---------------- mma.sync helpers ----------------
__device__ __forceinline__ uint32_t cvta_s(const void* p) {
    return (uint32_t)__cvta_generic_to_shared(p);
}
__device__ __forceinline__ void cp16(uint32_t dst, const void* src) {
    asm volatile("cp.async.cg.shared.global [%0], [%1], 16;" :: "r"(dst), "l"(src));
}
__device__ __forceinline__ void mma_bf16(float* d, const uint32_t* a, const uint32_t* b) {
    asm volatile(
        "mma.sync.aligned.m16n8k16.row.col.f32.bf16.bf16.f32 "
        "{%0,%1,%2,%3}, {%4,%5,%6,%7}, {%8,%9}, {%0,%1,%2,%3};"
        : "+f"(d[0]), "+f"(d[1]), "+f"(d[2]), "+f"(d[3])
        : "r"(a[0]), "r"(a[1]), "r"(a[2]), "r"(a[3]), "r"(b[0]), "r"(b[1]));
}

__device__ __forceinline__ void stage_load(uint32_t sb, int bm0, int bn0, int K,
                                           int k0, int tid) {
#pragma unroll
    for (int i = 0; i < 4; i++) {
        int gg = tid + i * 256;
        int r = gg >> 3, kk = (gg & 7) * 8;
        uint32_t d = sb + (uint32_t)r * ROWB + (uint32_t)kk * 2;
        size_t soA = (size_t)(bm0 + r) * K + k0 + kk;
        size_t soB = (size_t)(bn0 + r) * K + k0 + kk;
        cp16(d + AHO, d_abh + soA);
        cp16(d + ALO, d_abl + soA);
        cp16(d + BHO, d_wbh + soB);
        cp16(d + BLO, d_wbl + soB);
    }
    asm volatile("cp.async.commit_group;" ::: "memory");
}

// ---------------- bf16 3-term tensor-core GEMM: d_hl[M,256] = A @ W ----------------
__global__ void __launch_bounds__(256) k_gemm_mma(int K) {
    extern __shared__ char smem[];
    uint32_t sbase = cvta_s(smem);
    int tid = threadIdx.x, w = tid >> 5, lane = tid & 31;
    int bm0 = blockIdx.x * BM, bn0 = blockIdx.y * BN;
    int wm = w >> 1, wn = w & 1;
    int nch = K / BK;

    float acc[2][8][4];
#pragma unroll
    for (int mt = 0; mt < 2; mt++)
#pragma unroll
        for (int nt = 0; nt < 8; nt++)
#pragma unroll
            for (int j = 0; j < 4; j++) acc[mt][nt][j] = 0.f;

    stage_load(sbase, bm0, bn0, K, 0, tid);

    for (int c = 0; c < nch; c++) {
        if (c + 1 < nch) {
            stage_load(sbase + ((c + 1) & 1) * SSZ, bm0, bn0, K, (c + 1) * BK, tid);
            asm volatile("cp.async.wait_group 1;" ::: "memory");
        } else {
            asm volatile("cp.async.wait_group 0;" ::: "memory");
        }
        __syncthreads();

        const char* base = smem + (c & 1) * SSZ;
        int ar = wm * 32 + (lane >> 2);
        int kb2base = (lane & 3) * 4;
#pragma unroll
        for (int ks = 0; ks < 4; ks++) {
            int kb2 = ks * 32 + kb2base;
            uint32_t a_h[2][4], a_l[2][4];
#pragma unroll
            for (int mt = 0; mt < 2; mt++) {
                int r0 = (ar + mt * 16) * ROWB + kb2;
                int r1 = r0 + 8 * ROWB;
                a_h[mt][0] = *(const uint32_t*)(base + AHO + r0);
                a_h[mt][1] = *(const uint32_t*)(base + AHO + r1);
                a_h[mt][2] = *(const uint32_t*)(base + AHO + r0 + 16);
                a_h[mt][3] = *(const uint32_t*)(base + AHO + r1 + 16);
                a_l[mt][0] = *(const uint32_t*)(base + ALO + r0);
                a_l[mt][1] = *(const uint32_t*)(base + ALO + r1);
                a_l[mt][2] = *(const uint32_t*)(base + ALO + r0 + 16);
                a_l[mt][3] = *(const uint32_t*)(base + ALO + r1 + 16);
            }
#pragma unroll
            for (int nt = 0; nt < 8; nt++) {
                int n0 = (wn * 64 + nt * 8 + (lane >> 2)) * ROWB + kb2;
                uint32_t b_h[2], b_l[2];
                b_h[0] = *(const uint32_t*)(base + BHO + n0);
                b_h[1] = *(const uint32_t*)(base + BHO + n0 + 16);
                b_l[0] = *(const uint32_t*)(base + BLO + n0);
                b_l[1] = *(const uint32_t*)(base + BLO + n0 + 16);
#pragma unroll
                for (int mt = 0; mt < 2; mt++) {
                    mma_bf16(acc[mt][nt], a_h[mt], b_h);
                    mma_bf16(acc[mt][nt], a_h[mt], b_l);
                    mma_bf16(acc[mt][nt], a_l[mt], b_h);
                }
            }
        }
        __syncthreads();
    }

    // epilogue
#pragma unroll
    for (int mt = 0; mt < 2; mt++) {
        int r = bm0 + wm * 32 + mt * 16 + (lane >> 2);
#pragma unroll
        for (int nt = 0; nt < 8; nt++) {
            int cc = bn0 + wn * 64 + nt * 8 + (lane & 3) * 2;
            if (r < NN)
                *(float2*)(d_hl + (size_t)r * 256 + cc) =
                    make_float2(acc[mt][nt][0], acc[mt][nt][1]);
            if (r + 8 < NN)
                *(float2*)(d_hl + (size_t)(r + 8) * 256 + cc) =
                    make_float2(acc[mt][nt][2], acc[mt][nt][3]);
        }
    }
}

// ---------------- attention scores ----------------
__global__ void k_scores(const float* __restrict__ asrc, const float* __restrict__ adst) {
    int warp = (blockIdx.x * blockDim.x + threadIdx.x) >> 5;
    int lane = threadIdx.x & 31;
    if (warp >= NN) return;
    int n = warp;
    const float4* hl4 = (const float4*)d_hl;
    float4 x0 = hl4[(size_t)n * 64 + lane * 2];
    float4 x1 = hl4[(size_t)n * 64 + lane * 2 + 1];
    const float4* as4 = (const float4*)asrc;
    const float4* ad4 = (const float4*)adst;
    float4 s0 = as4[lane * 2], s1 = as4[lane * 2 + 1];
    float4 t0 = ad4[lane * 2], t1 = ad4[lane * 2 + 1];
    float ps = x0.x * s0.x + x0.y * s0.y + x0.z * s0.z + x0.w * s0.w
             + x1.x * s1.x + x1.y * s1.y + x1.z * s1.z + x1.w * s1.w;
    float pd = x0.x * t0.x + x0.y * t0.y + x0.z * t0.z + x0.w * t0.w
             + x1.x * t1.x + x1.y * t1.y + x1.z * t1.z + x1.w * t1.w;
    ps += __shfl_xor_sync(~0u, ps, 1); ps += __shfl_xor_sync(~0u, ps, 2);
    pd += __shfl_xor_sync(~0u, pd, 1); pd += __shfl_xor_sync(~0u, pd, 2);
    if ((lane & 3) == 0) {
        int h = lane >> 2;
        d_ssrc[n * 8 + h] = ps;
        d_sdst[n * 8 + h] = pd;
    }
}

__device__ __forceinline__ float leaky(float x) { return x > 0.f ? x : NEG_SLOPE * x; }

// ---------------- aggregation + bias + BN + res + ELU + bf16 split out ----------------
__global__ void k_agg(const float* __restrict__ bias, const float* __restrict__ gam,
                      const float* __restrict__ bet, const float* __restrict__ mu,
                      const float* __restrict__ var, int useRes) {
    int warp = (blockIdx.x * blockDim.x + threadIdx.x) >> 5;
    int lane = threadIdx.x & 31;
    if (warp >= NN) return;
    int n = warp;
    int beg = d_off[n], end = d_off[n + 1];
    int h = lane >> 2;

    float sd8[8];
    {
        const float4* p = (const float4*)(d_sdst + n * 8);
        float4 a = p[0], b = p[1];
        sd8[0] = a.x; sd8[1] = a.y; sd8[2] = a.z; sd8[3] = a.w;
        sd8[4] = b.x; sd8[5] = b.y; sd8[6] = b.z; sd8[7] = b.w;
    }
    float m8[8], z8[8];
#pragma unroll
    for (int i = 0; i < 8; i++) { m8[i] = -1e30f; z8[i] = 0.f; }

    for (int e = beg + lane; e < end; e += 32) {
        int s = d_es[e];
        const float4* p = (const float4*)(d_ssrc + s * 8);
        float4 a = p[0], b = p[1];
        float sv[8] = {a.x, a.y, a.z, a.w, b.x, b.y, b.z, b.w};
#pragma unroll
        for (int i = 0; i < 8; i++) {
            float al = leaky(sv[i] + sd8[i]);
            float mn = fmaxf(m8[i], al);
            z8[i] = z8[i] * __expf(m8[i] - mn) + __expf(al - mn);
            m8[i] = mn;
        }
    }
#pragma unroll
    for (int i = 0; i < 8; i++) {
        float m = m8[i], z = z8[i];
#pragma unroll
        for (int o = 16; o; o >>= 1) {
            float mo = __shfl_xor_sync(~0u, m, o);
            float zo = __shfl_xor_sync(~0u, z, o);
            float mn = fmaxf(m, mo);
            z = z * __expf(m - mn) + zo * __expf(mo - mn);
            m = mn;
        }
        m8[i] = m; z8[i] = z;
    }
    float my_m = 0.f, my_z = 0.f, my_sd = 0.f;
#pragma unroll
    for (int i = 0; i < 8; i++)
        if (h == i) { my_m = m8[i]; my_z = z8[i]; my_sd = sd8[i]; }
    float inv = 1.f / (my_z + 1e-16f);

    const float4* hl4 = (const float4*)d_hl;
    float4 acc0 = make_float4(0.f, 0.f, 0.f, 0.f);
    float4 acc1 = make_float4(0.f, 0.f, 0.f, 0.f);
    for (int e = beg; e < end; e++) {
        int s = d_es[e];
        float sv = __ldg(d_ssrc + s * 8 + h);
        float coef = __expf(leaky(sv + my_sd) - my_m) * inv;
        float4 v0 = hl4[(size_t)s * 64 + lane * 2];
        float4 v1 = hl4[(size_t)s * 64 + lane * 2 + 1];
        acc0.x += v0.x * coef; acc0.y += v0.y * coef;
        acc0.z += v0.z * coef; acc0.w += v0.w * coef;
        acc1.x += v1.x * coef; acc1.y += v1.y * coef;
        acc1.z += v1.z * coef; acc1.w += v1.w * coef;
    }

    int col = lane * 8;
    float4 b0 = *(const float4*)(bias + col), b1 = *(const float4*)(bias + col + 4);
    float4 g0 = *(const float4*)(gam + col),  g1 = *(const float4*)(gam + col + 4);
    float4 e0 = *(const float4*)(bet + col),  e1 = *(const float4*)(bet + col + 4);
    float4 u0 = *(const float4*)(mu + col),   u1 = *(const float4*)(mu + col + 4);
    float4 w0 = *(const float4*)(var + col),  w1 = *(const float4*)(var + col + 4);
    float4* act4 = (float4*)d_actbuf;
    float4 r0 = make_float4(0.f, 0.f, 0.f, 0.f), r1 = r0;
    if (useRes) {
        r0 = act4[(size_t)n * 64 + lane * 2];
        r1 = act4[(size_t)n * 64 + lane * 2 + 1];
    }
    float vin[8]  = {acc0.x, acc0.y, acc0.z, acc0.w, acc1.x, acc1.y, acc1.z, acc1.w};
    float bb[8]   = {b0.x, b0.y, b0.z, b0.w, b1.x, b1.y, b1.z, b1.w};
    float gg_[8]  = {g0.x, g0.y, g0.z, g0.w, g1.x, g1.y, g1.z, g1.w};
    float ee_[8]  = {e0.x, e0.y, e0.z, e0.w, e1.x, e1.y, e1.z, e1.w};
    float uu[8]   = {u0.x, u0.y, u0.z, u0.w, u1.x, u1.y, u1.z, u1.w};
    float vv[8]   = {w0.x, w0.y, w0.z, w0.w, w1.x, w1.y, w1.z, w1.w};
    float rr[8]   = {r0.x, r0.y, r0.z, r0.w, r1.x, r1.y, r1.z, r1.w};
    float outv[8];
#pragma unroll
    for (int j = 0; j < 8; j++) {
        float v = vin[j] + bb[j];
        v = (v - uu[j]) * rsqrtf(vv[j] + BN_EPS) * gg_[j] + ee_[j];
        if (useRes) v += rr[j];
        outv[j] = v > 0.f ? v : expm1f(v);
    }
    act4[(size_t)n * 64 + lane * 2]     = make_float4(outv[0], outv[1], outv[2], outv[3]);
    act4[(size_t)n * 64 + lane * 2 + 1] = make_float4(outv[4], outv[5], outv[6], outv[7]);

    // bf16 hi/lo split for the next layer's tensor-core GEMM
    uint32_t ph[4], pl[4];
#pragma unroll
    for (int j = 0; j < 4; j++) {
        __nv_bfloat16 h0 = __float2bfloat16(outv[2 * j]);
        __nv_bfloat16 h1 = __float2bfloat16(outv[2 * j + 1]);
        __nv_bfloat16 l0 = __float2bfloat16(outv[2 * j]     - __bfloat162float(h0));
        __nv_bfloat16 l1 = __float2bfloat16(outv[2 * j + 1] - __bfloat162float(h1));
        ph[j] = (uint32_t)__bfloat16_as_ushort(h0) | ((uint32_t)__bfloat16_as_ushort(h1) << 16);
        pl[j] = (uint32_t)__bfloat16_as_ushort(l0) | ((uint32_t)__bfloat16_as_ushort(l1) << 16);
    }
    *(uint4*)(d_abh + (size_t)n * 256 + col) = make_uint4(ph[0], ph[1], ph[2], ph[3]);
    *(uint4*)(d_abl + (size_t)n * 256 + col) = make_uint4(pl[0], pl[1], pl[2], pl[3]);
}

// ---------------- pooling + output heads ----------------
__device__ __forceinline__ int lbound(const int* __restrict__ a, int n, int v) {
    int lo = 0, hi = n;
    while (lo < hi) {
        int mid = (lo + hi) >> 1;
        if (a[mid] < v) lo = mid + 1; else hi = mid;
    }
    return lo;
}

__global__ void k_pool(const int* __restrict__ batch,
                       const float* __restrict__ ow0, const float* __restrict__ ob0,
                       const float* __restrict__ ow1, const float* __restrict__ ob1,
                       float* __restrict__ out) {
    int g = blockIdx.x;
    int t = threadIdx.x;
    int lo = lbound(batch, NN, g);
    int hi = lbound(batch, NN, g + 1);
    __shared__ float pooled[3 * HIDD];
    __shared__ float sacc[6];

    int c = t;
    float sum = 0.f, mx = -1e30f;
    for (int n = lo; n < hi; n++) {
        float v = d_actbuf[(size_t)n * 256 + c];
        sum += v;
        mx = fmaxf(mx, v);
    }
    int cnt = hi - lo;
    pooled[c]       = sum / fmaxf((float)cnt, 1.f);
    pooled[256 + c] = sum;
    pooled[512 + c] = (cnt > 0) ? mx : 0.f;
    if (t < 6) sacc[t] = 0.f;
    __syncthreads();

    float p0[3] = {0.f, 0.f, 0.f}, p1[3] = {0.f, 0.f, 0.f};
    for (int j = t; j < 768; j += 256) {
        float v = pooled[j];
#pragma unroll
        for (int k = 0; k < 3; k++) {
            p0[k] += v * ow0[j * 3 + k];
            p1[k] += v * ow1[j * 3 + k];
        }
    }
#pragma unroll
    for (int k = 0; k < 3; k++) {
        atomicAdd(&sacc[k], p0[k]);
        atomicAdd(&sacc[3 + k], p1[k]);
    }
    __syncthreads();
    if (t < 3) {
        out[g * 3 + t]          = sacc[t]     + ob0[t];
        out[GG * 3 + g * 3 + t] = sacc[3 + t] + ob1[t];
    }
}

// ---------------- launch ----------------
extern "C" void kernel_launch(void* const* d_in, const int* in_sizes, int n_in,
                              void* d_out, int out_size) {
    const float* x     = (const float*)d_in[0];
    const int*   ei    = (const int*)d_in[1];
    const int*   batch = (const int*)d_in[2];

    const float* W[3]  = {(const float*)d_in[3],  (const float*)d_in[11], (const float*)d_in[19]};
    const float* AS[3] = {(const float*)d_in[4],  (const float*)d_in[12], (const float*)d_in[20]};
    const float* AD[3] = {(const float*)d_in[5],  (const float*)d_in[13], (const float*)d_in[21]};
    const float* BI[3] = {(const float*)d_in[6],  (const float*)d_in[14], (const float*)d_in[22]};
    const float* GA[3] = {(const float*)d_in[7],  (const float*)d_in[15], (const float*)d_in[23]};
    const float* BE[3] = {(const float*)d_in[8],  (const float*)d_in[16], (const float*)d_in[24]};
    const float* MU[3] = {(const float*)d_in[9],  (const float*)d_in[17], (const float*)d_in[25]};
    const float* VA[3] = {(const float*)d_in[10], (const float*)d_in[18], (const float*)d_in[26]};
    const float* ow0 = (const float*)d_in[27];
    const float* ob0 = (const float*)d_in[28];
    const float* ow1 = (const float*)d_in[29];
    const float* ob1 = (const float*)d_in[30];
    float* out = (float*)d_out;

    static int smem_set = 0;
    if (!smem_set) {
        cudaFuncSetAttribute(k_gemm_mma, cudaFuncAttributeMaxDynamicSharedMemorySize,
                             SMEM_TOTAL);
        smem_set = 1;
    }

    k_init_deg<<<cdiv(NN, 256), 256>>>();
    k_count<<<cdiv(NE, 256), 256>>>(ei + NE);
    k_scan<<<1, 1024>>>();
    k_scatter<<<cdiv(TE, 256), 256>>>(ei, ei + NE);

    k_cvtA<<<cdiv(NN * IN_DIM / 4, 256), 256>>>(x);

    for (int l = 0; l < 3; l++) {
        int K = (l == 0) ? IN_DIM : HIDD;
        k_prepW<<<cdiv(K * HIDD, 256), 256>>>(W[l], K);
        dim3 gg(NTILES, 2);
        k_gemm_mma<<<gg, 256, SMEM_TOTAL>>>(K);
        k_scores<<<cdiv(NN, 8), 256>>>(AS[l], AD[l]);
        k_agg<<<cdiv(NN, 8), 256>>>(BI[l], GA[l], BE[l], MU[l], VA[l], l > 0 ? 1 : 0);
    }
    k_pool<<<GG, 256>>>(batch, ow0, ob0, ow1, ob1, out);
}

// round 4
// speedup vs baseline: 1.3598x; 1.0276x over previous
#include <cuda_runtime.h>
#include <cuda_bf16.h>
#include <math.h>
#include <stdint.h>

#define NN      50000
#define NE      800000
#define TE      (NE + NN)
#define GG      512
#define IN_DIM  128
#define HIDD    256
#define HEADS   8
#define NEG_SLOPE 0.2f
#define BN_EPS  1e-5f

#define BM 128
#define BN 128
#define BK 64
#define NPAD    50176
#define NTILES  ((NN + BM - 1) / BM)     // 391

#define ROWB   144
#define TILEB  (128 * ROWB)
#define AHO    0
#define ALO    TILEB
#define BHO    (2 * TILEB)
#define BLO    (3 * TILEB)
#define SSZ    (4 * TILEB)
#define SMEM_TOTAL (2 * SSZ)             // 147456

// ---------------- scratch ----------------
__device__ float d_hl[NN * HIDD];
__device__ float d_actbuf[NN * HIDD];
__device__ float d_ssrc[NN * HEADS];
__device__ float d_sdst[NN * HEADS];
__device__ __nv_bfloat16 d_abh[NPAD * HIDD];
__device__ __nv_bfloat16 d_abl[NPAD * HIDD];
__device__ __nv_bfloat16 d_wbh[HIDD * HIDD];
__device__ __nv_bfloat16 d_wbl[HIDD * HIDD];
__device__ int d_off[NN + 1];
__device__ int d_cur[NN];
__device__ int d_es[TE];

static inline int cdiv(int a, int b) { return (a + b - 1) / b; }

// ---------------- CSR build ----------------
__global__ void k_init_deg() {
    int n = blockIdx.x * blockDim.x + threadIdx.x;
    if (n < NN) d_off[n] = 1;
}
__global__ void k_count(const int* __restrict__ dst) {
    int i = blockIdx.x * blockDim.x + threadIdx.x;
    if (i < NE / 4) {
        int4 v = ((const int4*)dst)[i];
        atomicAdd(&d_off[v.x], 1);
        atomicAdd(&d_off[v.y], 1);
        atomicAdd(&d_off[v.z], 1);
        atomicAdd(&d_off[v.w], 1);
    }
}
__global__ void k_scan() {
    __shared__ int s[1024];
    const int CH = (NN + 1023) / 1024;
    int t = threadIdx.x;
    int b = t * CH;
    int e = b + CH; if (e > NN) e = NN;
    int sum = 0;
    for (int i = b; i < e && i < NN; i++) sum += d_off[i];
    s[t] = sum;
    __syncthreads();
    for (int o = 1; o < 1024; o <<= 1) {
        int v = (t >= o) ? s[t - o] : 0;
        __syncthreads();
        s[t] += v;
        __syncthreads();
    }
    int run = s[t] - sum;
    for (int i = b; i < e && i < NN; i++) {
        int c = d_off[i];
        d_off[i] = run;
        d_cur[i] = run;
        run += c;
    }
    if (t == 0) d_off[NN] = TE;
}
__global__ void k_scatter(const int* __restrict__ src, const int* __restrict__ dst) {
    int i = blockIdx.x * blockDim.x + threadIdx.x;
    if (i < NE / 4) {
        int4 sv = ((const int4*)src)[i];
        int4 dv = ((const int4*)dst)[i];
        d_es[atomicAdd(&d_cur[dv.x], 1)] = sv.x;
        d_es[atomicAdd(&d_cur[dv.y], 1)] = sv.y;
        d_es[atomicAdd(&d_cur[dv.z], 1)] = sv.z;
        d_es[atomicAdd(&d_cur[dv.w], 1)] = sv.w;
    } else {
        int n = i - NE / 4;
        if (n < NN) d_es[atomicAdd(&d_cur[n], 1)] = n;
    }
}

// ---------------- input/weight bf16 split ----------------
__global__ void k_cvtA(const float* __restrict__ x) {
    int idx = blockIdx.x * blockDim.x + threadIdx.x;
    if (idx >= NN * IN_DIM / 4) return;
    float4 v = ((const float4*)x)[idx];
    float vv[4] = {v.x, v.y, v.z, v.w};
    unsigned short h[4], l[4];
#pragma unroll
    for (int j = 0; j < 4; j++) {
        __nv_bfloat16 hb = __float2bfloat16(vv[j]);
        __nv_bfloat16 lb = __float2bfloat16(vv[j] - __bfloat162float(hb));
        h[j] = __bfloat16_as_ushort(hb);
        l[j] = __bfloat16_as_ushort(lb);
    }
    uint2 ph = make_uint2((uint32_t)h[0] | ((uint32_t)h[1] << 16),
                          (uint32_t)h[2] | ((uint32_t)h[3] << 16));
    uint2 pl = make_uint2((uint32_t)l[0] | ((uint32_t)l[1] << 16),
                          (uint32_t)l[2] | ((uint32_t)l[3] << 16));
    *(uint2*)(d_abh + (size_t)idx * 4) = ph;
    *(uint2*)(d_abl + (size_t)idx * 4) = pl;
}

__global__ void k_prepW(const float* __restrict__ W, int K) {
    int idx = blockIdx.x * blockDim.x + threadIdx.x;
    if (idx >= K * HIDD) return;
    int k = idx / HIDD, n = idx % HIDD;
    float v = W[idx];
    __nv_bfloat16 hb = __float2bfloat16(v);
    __nv_bfloat16 lb = __float2bfloat16(v - __bfloat162float(hb));
    d_wbh[n * K + k] = hb;
    d_wbl[n * K + k] = lb;
}

// ---------------- mma helpers ----------------
__device__ __forceinline__ uint32_t cvta_s(const void* p) {
    return (uint32_t)__cvta_generic_to_shared(p);
}
__device__ __forceinline__ void cp16(uint32_t dst, const void* src) {
    asm volatile("cp.async.cg.shared.global [%0], [%1], 16;" :: "r"(dst), "l"(src));
}
__device__ __forceinline__ void mma_bf16(float* d, const uint32_t* a, const uint32_t* b) {
    asm volatile(
        "mma.sync.aligned.m16n8k16.row.col.f32.bf16.bf16.f32 "
        "{%0,%1,%2,%3}, {%4,%5,%6,%7}, {%8,%9}, {%0,%1,%2,%3};"
        : "+f"(d[0]), "+f"(d[1]), "+f"(d[2]), "+f"(d[3])
        : "r"(a[0]), "r"(a[1]), "r"(a[2]), "r"(a[3]), "r"(b[0]), "r"(b[1]));
}
__device__ __forceinline__ void ldm_x4(uint32_t* r, uint32_t addr) {
    asm volatile("ldmatrix.sync.aligned.m8n8.x4.shared.b16 {%0,%1,%2,%3}, [%4];"
                 : "=r"(r[0]), "=r"(r[1]), "=r"(r[2]), "=r"(r[3]) : "r"(addr));
}

__device__ __forceinline__ void stage_load(uint32_t sb, int bm0, int bn0, int K,
                                           int k0, int tid) {
#pragma unroll
    for (int i = 0; i < 4; i++) {
        int gg = tid + i * 256;
        int r = gg >> 3, kk = (gg & 7) * 8;
        uint32_t d = sb + (uint32_t)r * ROWB + (uint32_t)kk * 2;
        size_t soA = (size_t)(bm0 + r) * K + k0 + kk;
        size_t soB = (size_t)(bn0 + r) * K + k0 + kk;
        cp16(d + AHO, d_abh + soA);
        cp16(d + ALO, d_abl + soA);
        cp16(d + BHO, d_wbh + soB);
        cp16(d + BLO, d_wbl + soB);
    }
    asm volatile("cp.async.commit_group;" ::: "memory");
}

// ---------------- bf16 3-term tensor-core GEMM + fused scores ----------------
__global__ void __launch_bounds__(256) k_gemm_mma(int K, const float* __restrict__ asrc,
                                                  const float* __restrict__ adst) {
    extern __shared__ char smem[];
    uint32_t sbase = cvta_s(smem);
    int tid = threadIdx.x, w = tid >> 5, lane = tid & 31;
    int bm0 = blockIdx.x * BM, bn0 = blockIdx.y * BN;
    int wm = w >> 1, wn = w & 1;
    int nch = K / BK;

    float acc[2][8][4];
#pragma unroll
    for (int mt = 0; mt < 2; mt++)
#pragma unroll
        for (int nt = 0; nt < 8; nt++)
#pragma unroll
            for (int j = 0; j < 4; j++) acc[mt][nt][j] = 0.f;

    stage_load(sbase, bm0, bn0, K, 0, tid);

    uint32_t t8 = (uint32_t)(lane >> 3), r8 = (uint32_t)(lane & 7);

    for (int c = 0; c < nch; c++) {
        if (c + 1 < nch) {
            stage_load(sbase + ((c + 1) & 1) * SSZ, bm0, bn0, K, (c + 1) * BK, tid);
            asm volatile("cp.async.wait_group 1;" ::: "memory");
        } else {
            asm volatile("cp.async.wait_group 0;" ::: "memory");
        }
        __syncthreads();

        uint32_t stage = sbase + (c & 1) * SSZ;
#pragma unroll
        for (int ks = 0; ks < 4; ks++) {
            uint32_t kof = (uint32_t)ks * 32 + (t8 >> 1) * 16;
            uint32_t a_h[2][4], a_l[2][4];
#pragma unroll
            for (int mt = 0; mt < 2; mt++) {
                uint32_t arow = (uint32_t)(wm * 32 + mt * 16) + (t8 & 1) * 8 + r8;
                uint32_t aad = stage + arow * ROWB + kof;
                ldm_x4(a_h[mt], aad + AHO);
                ldm_x4(a_l[mt], aad + ALO);
            }
            uint32_t kofb = (uint32_t)ks * 32 + (t8 & 1) * 16;
#pragma unroll
            for (int ntp = 0; ntp < 4; ntp++) {
                uint32_t nrow = (uint32_t)(wn * 64 + ntp * 16) + (t8 >> 1) * 8 + r8;
                uint32_t bad = stage + nrow * ROWB + kofb;
                uint32_t b_h[4], b_l[4];
                ldm_x4(b_h, bad + BHO);
                ldm_x4(b_l, bad + BLO);
#pragma unroll
                for (int mt = 0; mt < 2; mt++) {
                    mma_bf16(acc[mt][2 * ntp],     a_h[mt], b_h);
                    mma_bf16(acc[mt][2 * ntp],     a_h[mt], b_l);
                    mma_bf16(acc[mt][2 * ntp],     a_l[mt], b_h);
                    mma_bf16(acc[mt][2 * ntp + 1], a_h[mt], b_h + 2);
                    mma_bf16(acc[mt][2 * ntp + 1], a_h[mt], b_l + 2);
                    mma_bf16(acc[mt][2 * ntp + 1], a_l[mt], b_h + 2);
                }
            }
        }
        __syncthreads();
    }

    // ---- fused attention scores: warp covers 64 cols = 2 complete heads ----
    float ss[2][2][2], sd[2][2][2];
#pragma unroll
    for (int mt = 0; mt < 2; mt++)
#pragma unroll
        for (int ro = 0; ro < 2; ro++)
#pragma unroll
            for (int hh = 0; hh < 2; hh++) { ss[mt][ro][hh] = 0.f; sd[mt][ro][hh] = 0.f; }

#pragma unroll
    for (int nt = 0; nt < 8; nt++) {
        int cc = bn0 + wn * 64 + nt * 8 + (lane & 3) * 2;
        float a0s = __ldg(asrc + cc), a1s = __ldg(asrc + cc + 1);
        float a0d = __ldg(adst + cc), a1d = __ldg(adst + cc + 1);
        int hh = nt >> 2;
#pragma unroll
        for (int mt = 0; mt < 2; mt++) {
            ss[mt][0][hh] += acc[mt][nt][0] * a0s + acc[mt][nt][1] * a1s;
            sd[mt][0][hh] += acc[mt][nt][0] * a0d + acc[mt][nt][1] * a1d;
            ss[mt][1][hh] += acc[mt][nt][2] * a0s + acc[mt][nt][3] * a1s;
            sd[mt][1][hh] += acc[mt][nt][2] * a0d + acc[mt][nt][3] * a1d;
        }
    }
#pragma unroll
    for (int mt = 0; mt < 2; mt++)
#pragma unroll
        for (int ro = 0; ro < 2; ro++)
#pragma unroll
            for (int hh = 0; hh < 2; hh++) {
                float vs = ss[mt][ro][hh], vd = sd[mt][ro][hh];
                vs += __shfl_xor_sync(~0u, vs, 1); vs += __shfl_xor_sync(~0u, vs, 2);
                vd += __shfl_xor_sync(~0u, vd, 1); vd += __shfl_xor_sync(~0u, vd, 2);
                if ((lane & 3) == 0) {
                    int r = bm0 + wm * 32 + mt * 16 + (lane >> 2) + ro * 8;
                    int h = (bn0 + wn * 64) / 32 + hh;
                    if (r < NN) {
                        d_ssrc[r * 8 + h] = vs;
                        d_sdst[r * 8 + h] = vd;
                    }
                }
            }

    // ---- write d_hl ----
#pragma unroll
    for (int mt = 0; mt < 2; mt++) {
        int r = bm0 + wm * 32 + mt * 16 + (lane >> 2);
#pragma unroll
        for (int nt = 0; nt < 8; nt++) {
            int cc = bn0 + wn * 64 + nt * 8 + (lane & 3) * 2;
            if (r < NN)
                *(float2*)(d_hl + (size_t)r * 256 + cc) =
                    make_float2(acc[mt][nt][0], acc[mt][nt][1]);
            if (r + 8 < NN)
                *(float2*)(d_hl + (size_t)(r + 8) * 256 + cc) =
                    make_float2(acc[mt][nt][2], acc[mt][nt][3]);
        }
    }
}

__device__ __forceinline__ float leaky(float x) { return x > 0.f ? x : NEG_SLOPE * x; }

// ---------------- aggregation + bias + BN + res + ELU + bf16 split out ----------------
__global__ void k_agg(const float* __restrict__ bias, const float* __restrict__ gam,
                      const float* __restrict__ bet, const float* __restrict__ mu,
                      const float* __restrict__ var, int useRes) {
    int warp = (blockIdx.x * blockDim.x + threadIdx.x) >> 5;
    int lane = threadIdx.x & 31;
    if (warp >= NN) return;
    int n = warp;
    int beg = d_off[n], end = d_off[n + 1];
    int h = lane >> 2;

    float sd8[8];
    {
        const float4* p = (const float4*)(d_sdst + n * 8);
        float4 a = p[0], b = p[1];
        sd8[0] = a.x; sd8[1] = a.y; sd8[2] = a.z; sd8[3] = a.w;
        sd8[4] = b.x; sd8[5] = b.y; sd8[6] = b.z; sd8[7] = b.w;
    }
    float m8[8], z8[8];
#pragma unroll
    for (int i = 0; i < 8; i++) { m8[i] = -1e30f; z8[i] = 0.f; }

    for (int e = beg + lane; e < end; e += 32) {
        int s = d_es[e];
        const float4* p = (const float4*)(d_ssrc + s * 8);
        float4 a = p[0], b = p[1];
        float sv[8] = {a.x, a.y, a.z, a.w, b.x, b.y, b.z, b.w};
#pragma unroll
        for (int i = 0; i < 8; i++) {
            float al = leaky(sv[i] + sd8[i]);
            float mn = fmaxf(m8[i], al);
            z8[i] = z8[i] * __expf(m8[i] - mn) + __expf(al - mn);
            m8[i] = mn;
        }
    }
#pragma unroll
    for (int i = 0; i < 8; i++) {
        float m = m8[i], z = z8[i];
#pragma unroll
        for (int o = 16; o; o >>= 1) {
            float mo = __shfl_xor_sync(~0u, m, o);
            float zo = __shfl_xor_sync(~0u, z, o);
            float mn = fmaxf(m, mo);
            z = z * __expf(m - mn) + zo * __expf(mo - mn);
            m = mn;
        }
        m8[i] = m; z8[i] = z;
    }
    float my_m = 0.f, my_z = 0.f, my_sd = 0.f;
#pragma unroll
    for (int i = 0; i < 8; i++)
        if (h == i) { my_m = m8[i]; my_z = z8[i]; my_sd = sd8[i]; }
    float inv = 1.f / (my_z + 1e-16f);

    const float4* hl4 = (const float4*)d_hl;
    float4 acc0 = make_float4(0.f, 0.f, 0.f, 0.f);
    float4 acc1 = make_float4(0.f, 0.f, 0.f, 0.f);
    for (int e = beg; e < end; e++) {
        int s = d_es[e];
        float sv = __ldg(d_ssrc + s * 8 + h);
        float coef = __expf(leaky(sv + my_sd) - my_m) * inv;
        float4 v0 = hl4[(size_t)s * 64 + lane * 2];
        float4 v1 = hl4[(size_t)s * 64 + lane * 2 + 1];
        acc0.x += v0.x * coef; acc0.y += v0.y * coef;
        acc0.z += v0.z * coef; acc0.w += v0.w * coef;
        acc1.x += v1.x * coef; acc1.y += v1.y * coef;
        acc1.z += v1.z * coef; acc1.w += v1.w * coef;
    }

    int col = lane * 8;
    float4 b0 = *(const float4*)(bias + col), b1 = *(const float4*)(bias + col + 4);
    float4 g0 = *(const float4*)(gam + col),  g1 = *(const float4*)(gam + col + 4);
    float4 e0 = *(const float4*)(bet + col),  e1 = *(const float4*)(bet + col + 4);
    float4 u0 = *(const float4*)(mu + col),   u1 = *(const float4*)(mu + col + 4);
    float4 w0 = *(const float4*)(var + col),  w1 = *(const float4*)(var + col + 4);
    float4* act4 = (float4*)d_actbuf;
    float4 r0 = make_float4(0.f, 0.f, 0.f, 0.f), r1 = r0;
    if (useRes) {
        r0 = act4[(size_t)n * 64 + lane * 2];
        r1 = act4[(size_t)n * 64 + lane * 2 + 1];
    }
    float vin[8]  = {acc0.x, acc0.y, acc0.z, acc0.w, acc1.x, acc1.y, acc1.z, acc1.w};
    float bb[8]   = {b0.x, b0.y, b0.z, b0.w, b1.x, b1.y, b1.z, b1.w};
    float gg_[8]  = {g0.x, g0.y, g0.z, g0.w, g1.x, g1.y, g1.z, g1.w};
    float ee_[8]  = {e0.x, e0.y, e0.z, e0.w, e1.x, e1.y, e1.z, e1.w};
    float uu[8]   = {u0.x, u0.y, u0.z, u0.w, u1.x, u1.y, u1.z, u1.w};
    float vv[8]   = {w0.x, w0.y, w0.z, w0.w, w1.x, w1.y, w1.z, w1.w};
    float rr[8]   = {r0.x, r0.y, r0.z, r0.w, r1.x, r1.y, r1.z, r1.w};
    float outv[8];
#pragma unroll
    for (int j = 0; j < 8; j++) {
        float v = vin[j] + bb[j];
        v = (v - uu[j]) * rsqrtf(vv[j] + BN_EPS) * gg_[j] + ee_[j];
        if (useRes) v += rr[j];
        outv[j] = v > 0.f ? v : expm1f(v);
    }
    act4[(size_t)n * 64 + lane * 2]     = make_float4(outv[0], outv[1], outv[2], outv[3]);
    act4[(size_t)n * 64 + lane * 2 + 1] = make_float4(outv[4], outv[5], outv[6], outv[7]);

    uint32_t ph[4], pl[4];
#pragma unroll
    for (int j = 0; j < 4; j++) {
        __nv_bfloat16 h0 = __float2bfloat16(outv[2 * j]);
        __nv_bfloat16 h1 = __float2bfloat16(outv[2 * j + 1]);
        __nv_bfloat16 l0 = __float2bfloat16(outv[2 * j]     - __bfloat162float(h0));
        __nv_bfloat16 l1 = __float2bfloat16(outv[2 * j + 1] - __bfloat162float(h1));
        ph[j] = (uint32_t)__bfloat16_as_ushort(h0) | ((uint32_t)__bfloat16_as_ushort(h1) << 16);
        pl[j] = (uint32_t)__bfloat16_as_ushort(l0) | ((uint32_t)__bfloat16_as_ushort(l1) << 16);
    }
    *(uint4*)(d_abh + (size_t)n * 256 + col) = make_uint4(ph[0], ph[1], ph[2], ph[3]);
    *(uint4*)(d_abl + (size_t)n * 256 + col) = make_uint4(pl[0], pl[1], pl[2], pl[3]);
}

// ---------------- pooling + output heads ----------------
__device__ __forceinline__ int lbound(const int* __restrict__ a, int n, int v) {
    int lo = 0, hi = n;
    while (lo < hi) {
        int mid = (lo + hi) >> 1;
        if (a[mid] < v) lo = mid + 1; else hi = mid;
    }
    return lo;
}

__global__ void k_pool(const int* __restrict__ batch,
                       const float* __restrict__ ow0, const float* __restrict__ ob0,
                       const float* __restrict__ ow1, const float* __restrict__ ob1,
                       float* __restrict__ out) {
    int g = blockIdx.x;
    int t = threadIdx.x;
    int lo = lbound(batch, NN, g);
    int hi = lbound(batch, NN, g + 1);
    __shared__ float pooled[3 * HIDD];
    __shared__ float sacc[6];

    int c = t;
    float sum = 0.f, mx = -1e30f;
    for (int n = lo; n < hi; n++) {
        float v = d_actbuf[(size_t)n * 256 + c];
        sum += v;
        mx = fmaxf(mx, v);
    }
    int cnt = hi - lo;
    pooled[c]       = sum / fmaxf((float)cnt, 1.f);
    pooled[256 + c] = sum;
    pooled[512 + c] = (cnt > 0) ? mx : 0.f;
    if (t < 6) sacc[t] = 0.f;
    __syncthreads();

    float p0[3] = {0.f, 0.f, 0.f}, p1[3] = {0.f, 0.f, 0.f};
    for (int j = t; j < 768; j += 256) {
        float v = pooled[j];
#pragma unroll
        for (int k = 0; k < 3; k++) {
            p0[k] += v * ow0[j * 3 + k];
            p1[k] += v * ow1[j * 3 + k];
        }
    }
#pragma unroll
    for (int k = 0; k < 3; k++) {
        atomicAdd(&sacc[k], p0[k]);
        atomicAdd(&sacc[3 + k], p1[k]);
    }
    __syncthreads();
    if (t < 3) {
        out[g * 3 + t]          = sacc[t]     + ob0[t];
        out[GG * 3 + g * 3 + t] = sacc[3 + t] + ob1[t];
    }
}

// ---------------- launch ----------------
extern "C" void kernel_launch(void* const* d_in, const int* in_sizes, int n_in,
                              void* d_out, int out_size) {
    const float* x     = (const float*)d_in[0];
    const int*   ei    = (const int*)d_in[1];
    const int*   batch = (const int*)d_in[2];

    const float* W[3]  = {(const float*)d_in[3],  (const float*)d_in[11], (const float*)d_in[19]};
    const float* AS[3] = {(const float*)d_in[4],  (const float*)d_in[12], (const float*)d_in[20]};
    const float* AD[3] = {(const float*)d_in[5],  (const float*)d_in[13], (const float*)d_in[21]};
    const float* BI[3] = {(const float*)d_in[6],  (const float*)d_in[14], (const float*)d_in[22]};
    const float* GA[3] = {(const float*)d_in[7],  (const float*)d_in[15], (const float*)d_in[23]};
    const float* BE[3] = {(const float*)d_in[8],  (const float*)d_in[16], (const float*)d_in[24]};
    const float* MU[3] = {(const float*)d_in[9],  (const float*)d_in[17], (const float*)d_in[25]};
    const float* VA[3] = {(const float*)d_in[10], (const float*)d_in[18], (const float*)d_in[26]};
    const float* ow0 = (const float*)d_in[27];
    const float* ob0 = (const float*)d_in[28];
    const float* ow1 = (const float*)d_in[29];
    const float* ob1 = (const float*)d_in[30];
    float* out = (float*)d_out;

    static int smem_set = 0;
    if (!smem_set) {
        cudaFuncSetAttribute(k_gemm_mma, cudaFuncAttributeMaxDynamicSharedMemorySize,
                             SMEM_TOTAL);
        smem_set = 1;
    }

    k_init_deg<<<cdiv(NN, 256), 256>>>();
    k_count<<<cdiv(NE / 4, 256), 256>>>(ei + NE);
    k_scan<<<1, 1024>>>();
    k_scatter<<<cdiv(NE / 4 + NN, 256), 256>>>(ei, ei + NE);

    k_cvtA<<<cdiv(NN * IN_DIM / 4, 256), 256>>>(x);

    for (int l = 0; l < 3; l++) {
        int K = (l == 0) ? IN_DIM : HIDD;
        k_prepW<<<cdiv(K * HIDD, 256), 256>>>(W[l], K);
        dim3 gg(NTILES, 2);
        k_gemm_mma<<<gg, 256, SMEM_TOTAL>>>(K, AS[l], AD[l]);
        k_agg<<<cdiv(NN, 8), 256>>>(BI[l], GA[l], BE[l], MU[l], VA[l], l > 0 ? 1 : 0);
    }
    k_pool<<<GG, 256>>>(batch, ow0, ob0, ow1, ob1, out);
}